// round 1
// baseline (speedup 1.0000x reference)
#include <cuda_runtime.h>
#include <math.h>

#define Bb 8
#define Nn 1024
#define Dd 768
#define Hh 12
#define DHh 64

// Scratch (static device globals: allocation-free at kernel_launch time)
__device__ float g_Q[(size_t)Bb*Hh*Nn*DHh];   // [b,h,n,d]
__device__ float g_K[(size_t)Bb*Hh*Nn*DHh];
__device__ float g_V[(size_t)Bb*Hh*Nn*DHh];
__device__ float g_S[(size_t)Bb*Hh*Nn*Nn];    // logits -> (in place) post-mixed attn
__device__ float g_C[(size_t)Bb*Nn*Dd];       // context [b,n,h*64+d]

// ---------------------------------------------------------------------------
// Shared 64x64x16 fp32 tile inner product.
// As: [64][16]  (row-major: [m_local][k])  -> broadcast scalar reads
// Bs: [16][68]  (padded, [k][n_local])     -> float4 reads, 16B-aligned rows
// ---------------------------------------------------------------------------
__device__ __forceinline__ void tile_fma(const float (*As)[16], const float (*Bs)[68],
                                         int ty4, int tx4, float acc[4][4]) {
    #pragma unroll
    for (int k = 0; k < 16; ++k) {
        float a[4];
        #pragma unroll
        for (int m = 0; m < 4; ++m) a[m] = As[ty4 + m][k];
        float4 bv = *(const float4*)&Bs[k][tx4];
        float bb[4] = {bv.x, bv.y, bv.z, bv.w};
        #pragma unroll
        for (int m = 0; m < 4; ++m)
            #pragma unroll
            for (int n = 0; n < 4; ++n)
                acc[m][n] += a[m] * bb[n];
    }
}

// ---------------------------------------------------------------------------
// K1: QKV projection.  x[8192,768] @ [Wq | Wkv] -> g_Q/g_K/g_V in [b,h,n,d]
// grid (36, 128): bx = 3*12 head-tiles (q,k,v x head), by = row tile
// ---------------------------------------------------------------------------
__global__ __launch_bounds__(256) void k_qkv(const float* __restrict__ x,
                                             const float* __restrict__ Wq,
                                             const float* __restrict__ Wkv) {
    __shared__ float As[64][16];
    __shared__ float Bs[16][68];
    const int tid = threadIdx.x;
    const int bx = blockIdx.x, by = blockIdx.y;
    const int mat = bx / 12, hd = bx % 12;
    const float* Bp; int ldb;
    if (mat == 0)      { Bp = Wq  + hd*64;       ldb = 768;  }
    else if (mat == 1) { Bp = Wkv + hd*64;       ldb = 1536; }
    else               { Bp = Wkv + 768 + hd*64; ldb = 1536; }
    const float* Ap = x + (size_t)by * 64 * 768;

    const int tx4 = (tid & 15) * 4, ty4 = (tid >> 4) * 4;
    const int lrow = tid >> 2,  lk4 = (tid & 3) * 4;   // A loader
    const int brow = tid >> 4,  bc4 = (tid & 15) * 4;  // B loader
    float acc[4][4] = {};

    for (int k0 = 0; k0 < 768; k0 += 16) {
        *(float4*)&As[lrow][lk4] = *(const float4*)(Ap + (size_t)lrow * 768 + k0 + lk4);
        *(float4*)&Bs[brow][bc4] = *(const float4*)(Bp + (size_t)(k0 + brow) * ldb + bc4);
        __syncthreads();
        tile_fma(As, Bs, ty4, tx4, acc);
        __syncthreads();
    }
    float* Ob = (mat == 0) ? g_Q : (mat == 1) ? g_K : g_V;
    const int b = by >> 4;
    const int n0 = (by & 15) * 64 + ty4;
    #pragma unroll
    for (int m = 0; m < 4; ++m) {
        float4 v = make_float4(acc[m][0], acc[m][1], acc[m][2], acc[m][3]);
        *(float4*)(Ob + ((size_t)(b * 12 + hd) * 1024 + n0 + m) * 64 + tx4) = v;
    }
}

// ---------------------------------------------------------------------------
// K2: raw dots = scale * Q @ K^T per (b,h).  grid (16 jt, 16 it, 96 bh)
// ---------------------------------------------------------------------------
__global__ __launch_bounds__(256) void k_dots() {
    __shared__ float As[64][16];
    __shared__ float Bs[16][68];
    const int tid = threadIdx.x;
    const int jt = blockIdx.x, it = blockIdx.y, bh = blockIdx.z;
    const float* Qp = g_Q + (size_t)bh * Nn * 64 + (size_t)it * 64 * 64;
    const float* Kp = g_K + (size_t)bh * Nn * 64 + (size_t)jt * 64 * 64;
    float* Sp = g_S + (size_t)bh * Nn * Nn;

    const int tx4 = (tid & 15) * 4, ty4 = (tid >> 4) * 4;
    const int lrow = tid >> 2, lk4 = (tid & 3) * 4;
    float acc[4][4] = {};

    for (int k0 = 0; k0 < 64; k0 += 16) {
        *(float4*)&As[lrow][lk4] = *(const float4*)(Qp + (size_t)lrow * 64 + k0 + lk4);
        float4 kv = *(const float4*)(Kp + (size_t)lrow * 64 + k0 + lk4);
        Bs[lk4 + 0][lrow] = kv.x;  Bs[lk4 + 1][lrow] = kv.y;
        Bs[lk4 + 2][lrow] = kv.z;  Bs[lk4 + 3][lrow] = kv.w;
        __syncthreads();
        tile_fma(As, Bs, ty4, tx4, acc);
        __syncthreads();
    }
    const float scale = 0.125f;  // DH^-0.5 = 1/8
    #pragma unroll
    for (int m = 0; m < 4; ++m) {
        float4 v = make_float4(acc[m][0]*scale, acc[m][1]*scale,
                               acc[m][2]*scale, acc[m][3]*scale);
        *(float4*)(Sp + (size_t)(it * 64 + ty4 + m) * 1024 + jt * 64 + tx4) = v;
    }
}

// ---------------------------------------------------------------------------
// K3: talking-heads: mix_pre -> softmax -> mix_post, fully fused, in-place on g_S.
// One CTA per (b,i). Each thread holds mixed[12 heads][4 j's] in registers.
// ---------------------------------------------------------------------------
__global__ __launch_bounds__(256) void k_mixsoft(const float* __restrict__ mix_pre,
                                                 const float* __restrict__ mix_post) {
    __shared__ float raw[12 * 512];
    __shared__ float pre[144], post[144];
    __shared__ float wred[96];
    __shared__ float gstat[24];  // [0..11] row max, [12..23] 1/sum
    const int t = threadIdx.x;
    const int b = blockIdx.x >> 10, i = blockIdx.x & 1023;
    if (t < 144) { pre[t] = mix_pre[t]; post[t] = mix_post[t]; }
    const size_t rowbase = (size_t)b * 12 * 1048576 + (size_t)i * 1024;

    float mx[12][4];
    #pragma unroll
    for (int g = 0; g < 12; ++g)
        mx[g][0] = mx[g][1] = mx[g][2] = mx[g][3] = 0.f;

    // mixed[g][j] = sum_h raw[h][j] * pre[h][g], two 512-wide j-chunks
    #pragma unroll
    for (int c = 0; c < 2; ++c) {
        __syncthreads();
        #pragma unroll
        for (int u = 0; u < 24; ++u) {
            int idx = u * 256 + t;
            int h = idx >> 9, j = idx & 511;
            raw[idx] = g_S[rowbase + (size_t)h * 1048576 + c * 512 + j];
        }
        __syncthreads();
        float rv[12][2];
        #pragma unroll
        for (int h = 0; h < 12; ++h) {
            rv[h][0] = raw[h * 512 + t];
            rv[h][1] = raw[h * 512 + t + 256];
        }
        #pragma unroll
        for (int g = 0; g < 12; ++g) {
            float a0 = mx[g][c * 2], a1 = mx[g][c * 2 + 1];
            #pragma unroll
            for (int h = 0; h < 12; ++h) {
                float p = pre[h * 12 + g];
                a0 += rv[h][0] * p;
                a1 += rv[h][1] * p;
            }
            mx[g][c * 2] = a0; mx[g][c * 2 + 1] = a1;
        }
    }

    const int lane = t & 31, wid = t >> 5;
    // row max per head
    #pragma unroll
    for (int g = 0; g < 12; ++g) {
        float m = fmaxf(fmaxf(mx[g][0], mx[g][1]), fmaxf(mx[g][2], mx[g][3]));
        #pragma unroll
        for (int o = 16; o > 0; o >>= 1) m = fmaxf(m, __shfl_xor_sync(0xffffffffu, m, o));
        if (lane == 0) wred[g * 8 + wid] = m;
    }
    __syncthreads();
    if (t < 12) {
        float m = wred[t * 8];
        #pragma unroll
        for (int w = 1; w < 8; ++w) m = fmaxf(m, wred[t * 8 + w]);
        gstat[t] = m;
    }
    __syncthreads();
    // exp + sum per head
    #pragma unroll
    for (int g = 0; g < 12; ++g) {
        float mg = gstat[g];
        float s = 0.f;
        #pragma unroll
        for (int r = 0; r < 4; ++r) { mx[g][r] = __expf(mx[g][r] - mg); s += mx[g][r]; }
        #pragma unroll
        for (int o = 16; o > 0; o >>= 1) s += __shfl_xor_sync(0xffffffffu, s, o);
        if (lane == 0) wred[g * 8 + wid] = s;
    }
    __syncthreads();
    if (t < 12) {
        float s = 0.f;
        #pragma unroll
        for (int w = 0; w < 8; ++w) s += wred[t * 8 + w];
        gstat[12 + t] = 1.0f / s;
    }
    __syncthreads();
    #pragma unroll
    for (int g = 0; g < 12; ++g) {
        float inv = gstat[12 + g];
        #pragma unroll
        for (int r = 0; r < 4; ++r) mx[g][r] *= inv;
    }
    // post-mix: out[h][j] = sum_g p[g][j] * mix_post[g][h]; write back in place
    #pragma unroll
    for (int h = 0; h < 12; ++h) {
        float o0 = 0.f, o1 = 0.f, o2 = 0.f, o3 = 0.f;
        #pragma unroll
        for (int g = 0; g < 12; ++g) {
            float p = post[g * 12 + h];
            o0 += mx[g][0] * p; o1 += mx[g][1] * p;
            o2 += mx[g][2] * p; o3 += mx[g][3] * p;
        }
        float* dst = g_S + rowbase + (size_t)h * 1048576;
        dst[t]       = o0; dst[t + 256] = o1;
        dst[t + 512] = o2; dst[t + 768] = o3;
    }
}

// ---------------------------------------------------------------------------
// K4: O = attn @ V per (b,h), written into context layout [b,n,h*64+d].
// grid (16 it, 96 bh)
// ---------------------------------------------------------------------------
__global__ __launch_bounds__(256) void k_av() {
    __shared__ float As[64][16];
    __shared__ float Bs[16][68];
    const int tid = threadIdx.x;
    const int it = blockIdx.x, bh = blockIdx.y;
    const int b = bh / 12, h = bh % 12;
    const float* Apm = g_S + (size_t)bh * Nn * Nn + (size_t)it * 64 * 1024;
    const float* Vp  = g_V + (size_t)bh * Nn * 64;

    const int tx4 = (tid & 15) * 4, ty4 = (tid >> 4) * 4;
    const int lrow = tid >> 2, lk4 = (tid & 3) * 4;
    const int brow = tid >> 4, bc4 = (tid & 15) * 4;
    float acc[4][4] = {};

    for (int k0 = 0; k0 < 1024; k0 += 16) {
        *(float4*)&As[lrow][lk4] = *(const float4*)(Apm + (size_t)lrow * 1024 + k0 + lk4);
        *(float4*)&Bs[brow][bc4] = *(const float4*)(Vp + (size_t)(k0 + brow) * 64 + bc4);
        __syncthreads();
        tile_fma(As, Bs, ty4, tx4, acc);
        __syncthreads();
    }
    #pragma unroll
    for (int m = 0; m < 4; ++m) {
        float4 v = make_float4(acc[m][0], acc[m][1], acc[m][2], acc[m][3]);
        *(float4*)(g_C + ((size_t)b * 1024 + it * 64 + ty4 + m) * 768 + h * 64 + tx4) = v;
    }
}

// ---------------------------------------------------------------------------
// K5: out = Ctx @ Wo + bo.  grid (12, 128)
// ---------------------------------------------------------------------------
__global__ __launch_bounds__(256) void k_out(const float* __restrict__ Wo,
                                             const float* __restrict__ bo,
                                             float* __restrict__ out) {
    __shared__ float As[64][16];
    __shared__ float Bs[16][68];
    const int tid = threadIdx.x;
    const int bx = blockIdx.x, by = blockIdx.y;
    const float* Apm = g_C + (size_t)by * 64 * 768;
    const float* Bp = Wo + bx * 64;

    const int tx4 = (tid & 15) * 4, ty4 = (tid >> 4) * 4;
    const int lrow = tid >> 2, lk4 = (tid & 3) * 4;
    const int brow = tid >> 4, bc4 = (tid & 15) * 4;
    float acc[4][4] = {};

    for (int k0 = 0; k0 < 768; k0 += 16) {
        *(float4*)&As[lrow][lk4] = *(const float4*)(Apm + (size_t)lrow * 768 + k0 + lk4);
        *(float4*)&Bs[brow][bc4] = *(const float4*)(Bp + (size_t)(k0 + brow) * 768 + bc4);
        __syncthreads();
        tile_fma(As, Bs, ty4, tx4, acc);
        __syncthreads();
    }
    float4 bias = *(const float4*)(bo + bx * 64 + tx4);
    #pragma unroll
    for (int m = 0; m < 4; ++m) {
        float4 v = make_float4(acc[m][0] + bias.x, acc[m][1] + bias.y,
                               acc[m][2] + bias.z, acc[m][3] + bias.w);
        *(float4*)(out + ((size_t)by * 64 + ty4 + m) * 768 + bx * 64 + tx4) = v;
    }
}

// ---------------------------------------------------------------------------
extern "C" void kernel_launch(void* const* d_in, const int* in_sizes, int n_in,
                              void* d_out, int out_size) {
    const float* x     = (const float*)d_in[0];
    const float* Wq    = (const float*)d_in[1];
    const float* Wkv   = (const float*)d_in[2];
    const float* mpre  = (const float*)d_in[3];
    const float* mpost = (const float*)d_in[4];
    const float* Wo    = (const float*)d_in[5];
    const float* bo    = (const float*)d_in[6];
    float* out = (float*)d_out;

    k_qkv   <<<dim3(36, 128),     256>>>(x, Wq, Wkv);
    k_dots  <<<dim3(16, 16, 96),  256>>>();
    k_mixsoft<<<8192,             256>>>(mpre, mpost);
    k_av    <<<dim3(16, 96),      256>>>();
    k_out   <<<dim3(12, 128),     256>>>(Wo, bo, out);
}